// round 15
// baseline (speedup 1.0000x reference)
#include <cuda_runtime.h>
#include <cuda_bf16.h>
#include <cstdint>

#define NT     262144
#define KC     512
#define DD     64
#define TPB    256
#define TK     128
#define NTILE  (NT / TK)
#define GRIDP  296
#define WIN    3.0e-3f
#define SCAP   512
#define RCAP   128

// smem layout
#define OFF_A    0                      // packed A frags: 16384
#define OFF_CBP  16384                  // pair-packed codebook 512*144 = 73728
#define OFF_C2   (OFF_CBP + 73728)      // 90112: fp32 norms [512]
#define OFF_S    (OFF_C2 + 2048)        // 92160: per-token S [128]
#define OFF_CAND (OFF_S + 512)          // 92672: packed (e,k) [128] u64
#define OFF_MINW (OFF_CAND + 1024)      // 93696: per-token per-cgrp mins [128][2]
#define OFF_Q    (OFF_MINW + 1024)      // 94720: single queue u32 [512]
#define OFF_QR   (OFF_Q + 2048)         // 96768: range queue u32 [128]
#define OFF_QC   (OFF_QR + 512)         // 97280: counters [2]
#define OFF_RED  (OFF_QC + 16)          // 97296
#define SMEM_TOTAL (OFF_RED + 64)       // 97360 -> 2 CTAs/SM

typedef unsigned long long u64;

__device__ double g_loss_acc;
__device__ unsigned int g_done_ctr;

__device__ __forceinline__ void mma16816(float* d, const unsigned* a,
                                         unsigned b0, unsigned b1) {
    asm volatile(
        "mma.sync.aligned.m16n8k16.row.col.f32.bf16.bf16.f32 "
        "{%0,%1,%2,%3}, {%4,%5,%6,%7}, {%8,%9}, {%0,%1,%2,%3};"
        : "+f"(d[0]), "+f"(d[1]), "+f"(d[2]), "+f"(d[3])
        : "r"(a[0]), "r"(a[1]), "r"(a[2]), "r"(a[3]), "r"(b0), "r"(b1));
}

__device__ __forceinline__ unsigned pk2(float x, float y) {
    __nv_bfloat162 b = __floats2bfloat162_rn(x, y);
    return *(unsigned*)&b;
}

// top-2 update: v1 <- 2nd-smallest, i0 <- index of smallest (strict <, keeps
// earlier index on tie -> ascending scan order preserves lowest-k)
#define UPD(vr0, vr1, ir0, s, kk)                                             \
    do {                                                                      \
        vr1 = fminf(vr1, fmaxf(vr0, (s)));                                    \
        ir0 = ((s) < vr0) ? (kk) : ir0;                                       \
        vr0 = fminf(vr0, (s));                                                \
    } while (0)

// Exact rescore (R2-proven rounding: fl(fl(S+c2)-fl(2*dot)), sequential
// ascending-d fp32 FMA) + packed atomicMin (equal e -> lower k = jnp ties).
__device__ __forceinline__ void rescore(const float* __restrict__ z,
                                        const float* __restrict__ cb,
                                        const float* s_c2, const float* s_S,
                                        u64* s_cand, size_t tok0, int row, int k) {
    const float4* rw = (const float4*)(cb + (size_t)k * DD);
    const float4* zr = (const float4*)(z + (tok0 + row) * DD);
    float d = 0.0f;
#pragma unroll
    for (int i = 0; i < DD / 4; ++i) {
        float4 a = rw[i], b = zr[i];
        d = __fmaf_rn(a.x, b.x, d); d = __fmaf_rn(a.y, b.y, d);
        d = __fmaf_rn(a.z, b.z, d); d = __fmaf_rn(a.w, b.w, d);
    }
    float e = __fsub_rn(__fadd_rn(s_S[row], s_c2[k]), __fmul_rn(2.0f, d));
    u64 pack = ((u64)__float_as_uint(e) << 32) | (unsigned)k;
    atomicMin(&s_cand[row], pack);
}

__global__ void __launch_bounds__(TPB, 2) vq_1pass(const float* __restrict__ z,
                                                   const float* __restrict__ cb,
                                                   float* __restrict__ out,
                                                   int loss_idx) {
    extern __shared__ char sm[];
    float*  s_c2   = (float*)(sm + OFF_C2);
    float2* s_c2p  = (float2*)(sm + OFF_C2);
    float*  s_S    = (float*)(sm + OFF_S);
    u64*    s_cand = (u64*)(sm + OFF_CAND);
    float*  s_minw = (float*)(sm + OFF_MINW);
    unsigned* s_q  = (unsigned*)(sm + OFF_Q);
    unsigned* s_qr = (unsigned*)(sm + OFF_QR);
    int*    s_qc   = (int*)(sm + OFF_QC);
    double* s_red  = (double*)(sm + OFF_RED);

    const int tid = threadIdx.x, wid = tid >> 5, lane = tid & 31;
    const int g = lane >> 2, tg = lane & 3;
    const int tgrp = wid >> 1;        // token group (32 tokens)
    const int cgrp = wid & 1;         // code group (256 codes)
    const float FINF = __int_as_float(0x7f800000);

    // ---- one-time: pair-packed bf16 codebook + exact fp32 norms ----
    {
        const float4* cf = (const float4*)cb;
        for (int idx = tid; idx < KC * DD / 4; idx += TPB) {
            int n = idx >> 4, c4 = idx & 15;
            float4 v = cf[idx];
            int k0 = c4 * 4;
            int ks = k0 >> 4;
            int r0 = k0 & 15, r1 = r0 + 2;
            char* base = sm + OFF_CBP + n * 144 + ks * 32;
            *(__nv_bfloat162*)(base + ((r0 >> 1) & 3) * 8 + (r0 >> 3) * 4) =
                __floats2bfloat162_rn(v.x, v.y);
            *(__nv_bfloat162*)(base + ((r1 >> 1) & 3) * 8 + (r1 >> 3) * 4) =
                __floats2bfloat162_rn(v.z, v.w);
        }
        for (int k = tid; k < KC; k += TPB) {
            const float4* r = (const float4*)(cb + (size_t)k * DD);
            float s = 0.0f;
#pragma unroll
            for (int i = 0; i < DD / 4; ++i) {
                float4 v = r[i];
                s = __fmaf_rn(v.x, v.x, s); s = __fmaf_rn(v.y, v.y, s);
                s = __fmaf_rn(v.z, v.z, s); s = __fmaf_rn(v.w, v.w, s);
            }
            s_c2[k] = s;
        }
    }

    double my_loss = 0.0;

    for (int tile = blockIdx.x; tile < NTILE; tile += GRIDP) {
        const size_t tok0 = (size_t)tile * TK;

        // ---- per-tile: fragment-packed A tile, exact S, cand, queues ----
#pragma unroll 1
        for (int u = tid; u < 1024; u += TPB) {
            int lane_u = u & 31, ks = (u >> 5) & 3, mtg = u >> 7;
            int gg = lane_u >> 2, tgg = lane_u & 3;
            int r = (mtg >> 1) * 32 + (mtg & 1) * 16 + gg;
            int c = ks * 16 + tgg * 2;
            const float* zb = z + (tok0 + r) * DD + c;
            float2 v0 = *(const float2*)(zb);
            float2 v1 = *(const float2*)(zb + 8 * DD);
            float2 v2 = *(const float2*)(zb + 8);
            float2 v3 = *(const float2*)(zb + 8 * DD + 8);
            uint4 pk;
            pk.x = pk2(v0.x, v0.y); pk.y = pk2(v1.x, v1.y);
            pk.z = pk2(v2.x, v2.y); pk.w = pk2(v3.x, v3.y);
            *(uint4*)(sm + OFF_A + u * 16) = pk;
        }
        if (tid < TK) {
            const float4* r = (const float4*)(z + (tok0 + tid) * DD);
            float s = 0.0f;
#pragma unroll
            for (int i = 0; i < DD / 4; ++i) {
                float4 v = r[i];
                s = __fmaf_rn(v.x, v.x, s); s = __fmaf_rn(v.y, v.y, s);
                s = __fmaf_rn(v.z, v.z, s); s = __fmaf_rn(v.w, v.w, s);
            }
            s_S[tid] = s;
            s_cand[tid] = 0xFFFFFFFFFFFFFFFFull;
        }
        if (tid == 0) { s_qc[0] = 0; s_qc[1] = 0; }
        __syncthreads();

        // ---- A fragments for this warp's 32 rows ----
        unsigned aF[2][4][4];
#pragma unroll
        for (int mt = 0; mt < 2; ++mt)
#pragma unroll
            for (int ks = 0; ks < 4; ++ks) {
                uint4 t = *(const uint4*)(sm + OFF_A +
                    (((tgrp * 2 + mt) * 4 + ks) << 9) + lane * 16);
                aF[mt][ks][0] = t.x; aF[mt][ks][1] = t.y;
                aF[mt][ks][2] = t.z; aF[mt][ks][3] = t.w;
            }

        const char* pw = sm + OFF_CBP + (cgrp * 256) * 144 + g * 144 + tg * 8;
        const int row0 = tgrp * 32 + g;

        // ====== SINGLE pass: per-lane top-2 values + best index per row =====
        float v00 = FINF, v01 = FINF, v02 = FINF, v03 = FINF;  // best
        float w00 = FINF, w01 = FINF, w02 = FINF, w03 = FINF;  // 2nd best
        int   i00 = 0,    i01 = 0,    i02 = 0,    i03 = 0;     // (j<<1)|b
        {
            uint2 bC0 = *(const uint2*)(pw),      bC1 = *(const uint2*)(pw + 32);
            uint2 bC2 = *(const uint2*)(pw + 64), bC3 = *(const uint2*)(pw + 96);
#pragma unroll 1
            for (int j = 0; j < 32; ++j) {
                const char* pn = pw + j * 1152 + 1152;
                uint2 n0, n1, n2, n3;
                if (j < 31) {
                    n0 = *(const uint2*)(pn);      n1 = *(const uint2*)(pn + 32);
                    n2 = *(const uint2*)(pn + 64); n3 = *(const uint2*)(pn + 96);
                }
                float a0[4] = {0, 0, 0, 0}, a1[4] = {0, 0, 0, 0};
                mma16816(a0, aF[0][0], bC0.x, bC0.y); mma16816(a1, aF[1][0], bC0.x, bC0.y);
                mma16816(a0, aF[0][1], bC1.x, bC1.y); mma16816(a1, aF[1][1], bC1.x, bC1.y);
                mma16816(a0, aF[0][2], bC2.x, bC2.y); mma16816(a1, aF[1][2], bC2.x, bC2.y);
                mma16816(a0, aF[0][3], bC3.x, bC3.y); mma16816(a1, aF[1][3], bC3.x, bC3.y);
                float2 cc = s_c2p[cgrp * 128 + 4 * j + tg];
                const int ja = j << 1, jb = ja | 1;
                float s;
                s = __fmaf_rn(-2.0f, a0[0], cc.x); UPD(v00, w00, i00, s, ja);
                s = __fmaf_rn(-2.0f, a0[1], cc.y); UPD(v00, w00, i00, s, jb);
                s = __fmaf_rn(-2.0f, a0[2], cc.x); UPD(v01, w01, i01, s, ja);
                s = __fmaf_rn(-2.0f, a0[3], cc.y); UPD(v01, w01, i01, s, jb);
                s = __fmaf_rn(-2.0f, a1[0], cc.x); UPD(v02, w02, i02, s, ja);
                s = __fmaf_rn(-2.0f, a1[1], cc.y); UPD(v02, w02, i02, s, jb);
                s = __fmaf_rn(-2.0f, a1[2], cc.x); UPD(v03, w03, i03, s, ja);
                s = __fmaf_rn(-2.0f, a1[3], cc.y); UPD(v03, w03, i03, s, jb);
                bC0 = n0; bC1 = n1; bC2 = n2; bC3 = n3;
            }
        }
        // warp-combine mins per row (over tg lanes)
        float m0 = v00, m1 = v01, m2 = v02, m3 = v03;
        m0 = fminf(m0, __shfl_xor_sync(0xFFFFFFFFu, m0, 1));
        m0 = fminf(m0, __shfl_xor_sync(0xFFFFFFFFu, m0, 2));
        m1 = fminf(m1, __shfl_xor_sync(0xFFFFFFFFu, m1, 1));
        m1 = fminf(m1, __shfl_xor_sync(0xFFFFFFFFu, m1, 2));
        m2 = fminf(m2, __shfl_xor_sync(0xFFFFFFFFu, m2, 1));
        m2 = fminf(m2, __shfl_xor_sync(0xFFFFFFFFu, m2, 2));
        m3 = fminf(m3, __shfl_xor_sync(0xFFFFFFFFu, m3, 1));
        m3 = fminf(m3, __shfl_xor_sync(0xFFFFFFFFu, m3, 2));
        if (tg == 0) {
            s_minw[(row0)      * 2 + cgrp] = m0;
            s_minw[(row0 + 8)  * 2 + cgrp] = m1;
            s_minw[(row0 + 16) * 2 + cgrp] = m2;
            s_minw[(row0 + 24) * 2 + cgrp] = m3;
        }
        __syncthreads();

        // push candidates: range entry if 2nd-best also inside window (the
        // lane may have discarded window hits), else single best entry
        {
            const int kbase = cgrp * 256 + tg * 2;
            const unsigned rtag = (unsigned)((cgrp << 2) | tg);
#pragma unroll
            for (int rr = 0; rr < 4; ++rr) {
                const int row = row0 + rr * 8;
                float v0r = (rr == 0) ? v00 : (rr == 1) ? v01 : (rr == 2) ? v02 : v03;
                float w0r = (rr == 0) ? w00 : (rr == 1) ? w01 : (rr == 2) ? w02 : w03;
                int   i0r = (rr == 0) ? i00 : (rr == 1) ? i01 : (rr == 2) ? i02 : i03;
                float thr = fminf(s_minw[row * 2], s_minw[row * 2 + 1]) + WIN;
                if (w0r < thr) {
                    int sl = atomicAdd(&s_qc[1], 1);
                    if (sl < RCAP) s_qr[sl] = ((unsigned)row << 3) | rtag;
                } else if (v0r < thr) {
                    int k = kbase + ((i0r >> 1) << 3) + (i0r & 1);
                    int sl = atomicAdd(&s_qc[0], 1);
                    if (sl < SCAP) s_q[sl] = ((unsigned)row << 9) | (unsigned)k;
                }
            }
        }
        __syncthreads();

        // ---- Drain queues: cooperative exact rescore ----
        {
            int ns = s_qc[0], nr = s_qc[1];
            if (ns > SCAP || nr > RCAP) {
                if (tid < TK) {   // overflow (prob ~0): full exact scan
                    float S = s_S[tid];
                    u64 best = 0xFFFFFFFFFFFFFFFFull;
                    for (int k = 0; k < KC; ++k) {
                        const float4* rw = (const float4*)(cb + (size_t)k * DD);
                        const float4* zr = (const float4*)(z + (tok0 + tid) * DD);
                        float d = 0.0f;
#pragma unroll
                        for (int i = 0; i < DD / 4; ++i) {
                            float4 a = rw[i], b = zr[i];
                            d = __fmaf_rn(a.x, b.x, d); d = __fmaf_rn(a.y, b.y, d);
                            d = __fmaf_rn(a.z, b.z, d); d = __fmaf_rn(a.w, b.w, d);
                        }
                        float e = __fsub_rn(__fadd_rn(S, s_c2[k]), __fmul_rn(2.0f, d));
                        u64 p = ((u64)__float_as_uint(e) << 32) | (unsigned)k;
                        if (p < best) best = p;
                    }
                    atomicMin(&s_cand[tid], best);
                }
            } else {
                for (int i = tid; i < ns; i += TPB) {
                    unsigned e = s_q[i];
                    rescore(z, cb, s_c2, s_S, s_cand, tok0, (int)(e >> 9), (int)(e & 511u));
                }
                for (int w = tid; w < nr * 64; w += TPB) {
                    unsigned e = s_qr[w >> 6];
                    int sub = w & 63;
                    int row = (int)(e >> 3);
                    int k = ((int)((e >> 2) & 1u)) * 256 + ((int)(e & 3u)) * 2
                          + (sub >> 1) * 8 + (sub & 1);
                    rescore(z, cb, s_c2, s_S, s_cand, tok0, row, k);
                }
            }
        }
        __syncthreads();

        // ---- Epilogue (threads 0..127): STE output + loss partial ----
        if (tid < TK) {
            int bk = (int)(s_cand[tid] & 0xFFFFFFFFull);
            const float4* q  = (const float4*)(cb + (size_t)bk * DD);
            const float4* zr = (const float4*)(z + (tok0 + tid) * DD);
            float4* op = (float4*)(out + (tok0 + tid) * DD);
            float lacc = 0.0f;
#pragma unroll
            for (int i = 0; i < DD / 4; ++i) {
                float4 cv = q[i], zv = zr[i];
                float4 o; float dx;
                dx = __fsub_rn(cv.x, zv.x); o.x = __fadd_rn(zv.x, dx); lacc = __fmaf_rn(dx, dx, lacc);
                dx = __fsub_rn(cv.y, zv.y); o.y = __fadd_rn(zv.y, dx); lacc = __fmaf_rn(dx, dx, lacc);
                dx = __fsub_rn(cv.z, zv.z); o.z = __fadd_rn(zv.z, dx); lacc = __fmaf_rn(dx, dx, lacc);
                dx = __fsub_rn(cv.w, zv.w); o.w = __fadd_rn(zv.w, dx); lacc = __fmaf_rn(dx, dx, lacc);
                op[i] = o;
            }
            my_loss += (double)lacc;
        }
        __syncthreads();
    }

    // ---- final loss reduction ----
    double dacc = my_loss;
#pragma unroll
    for (int o = 16; o > 0; o >>= 1)
        dacc += __shfl_down_sync(0xFFFFFFFFu, dacc, o);
    if (lane == 0) s_red[wid] = dacc;
    __syncthreads();
    if (tid == 0) {
        double t = 0.0;
#pragma unroll
        for (int w = 0; w < TPB / 32; ++w) t += s_red[w];
        atomicAdd(&g_loss_acc, t);
        __threadfence();
        unsigned int prev = atomicAdd(&g_done_ctr, 1u);
        if (prev == GRIDP - 1) {
            double m = atomicAdd(&g_loss_acc, 0.0) / (double)((long long)NT * DD);
            float m32 = (float)m;
            out[loss_idx] = __fadd_rn(m32, __fmul_rn(0.25f, m32));
            g_loss_acc = 0.0;
            __threadfence();
            g_done_ctr = 0u;
        }
    }
}

extern "C" void kernel_launch(void* const* d_in, const int* in_sizes, int n_in,
                              void* d_out, int out_size) {
    const float* z;
    const float* cb;
    if (in_sizes[0] == NT * DD) {
        z = (const float*)d_in[0];
        cb = (const float*)d_in[1];
    } else {
        z = (const float*)d_in[1];
        cb = (const float*)d_in[0];
    }
    float* out = (float*)d_out;

    cudaFuncSetAttribute(vq_1pass, cudaFuncAttributeMaxDynamicSharedMemorySize,
                         SMEM_TOTAL);
    vq_1pass<<<GRIDP, TPB, SMEM_TOTAL>>>(z, cb, out, out_size - 1);
}

// round 16
// speedup vs baseline: 1.3641x; 1.3641x over previous
#include <cuda_runtime.h>
#include <cuda_bf16.h>
#include <cstdint>

#define NT     262144
#define KC     512
#define DD     64
#define TPB    256
#define TK     128
#define NTILE  (NT / TK)
#define GRIDP  296
#define WIN    3.0e-3f
#define QCAP   1024
#define RS     72                      // z-tile row stride in bf16 (144B)

// smem layout
#define OFF_Z    0                      // bf16 z row tile 128*144 = 18432
#define OFF_CBP  18432                  // pair-packed codebook 512*144 = 73728
#define OFF_C2   (OFF_CBP + 73728)      // 92160: fp32 norms [512]
#define OFF_S    (OFF_C2 + 2048)        // 94208: per-token S [128]
#define OFF_CAND (OFF_S + 512)          // 94720: packed (e,k) [128] u64
#define OFF_MINW (OFF_CAND + 1024)      // 95744: per-token per-cgrp mins [128][2]
#define OFF_Q    (OFF_MINW + 1024)      // 96768: hit queue u32 [1024]
#define OFF_QC   (OFF_Q + 4096)         // 100864
#define OFF_RED  (OFF_QC + 16)          // 100880
#define SMEM_TOTAL (OFF_RED + 64)       // 100944 -> 2 CTAs/SM

typedef unsigned long long u64;

__device__ double g_loss_acc;
__device__ unsigned int g_done_ctr;

__device__ __forceinline__ void mma16816(float* d, const unsigned* a,
                                         unsigned b0, unsigned b1) {
    asm volatile(
        "mma.sync.aligned.m16n8k16.row.col.f32.bf16.bf16.f32 "
        "{%0,%1,%2,%3}, {%4,%5,%6,%7}, {%8,%9}, {%0,%1,%2,%3};"
        : "+f"(d[0]), "+f"(d[1]), "+f"(d[2]), "+f"(d[3])
        : "r"(a[0]), "r"(a[1]), "r"(a[2]), "r"(a[3]), "r"(b0), "r"(b1));
}

// Exact rescore (R2-proven rounding: fl(fl(S+c2)-fl(2*dot)), sequential
// ascending-d fp32 FMA) + packed atomicMin (equal e -> lower k = jnp ties).
__device__ __forceinline__ void rescore(const float* __restrict__ z,
                                        const float* __restrict__ cb,
                                        const float* s_c2, const float* s_S,
                                        u64* s_cand, size_t tok0, int row, int k) {
    const float4* rw = (const float4*)(cb + (size_t)k * DD);
    const float4* zr = (const float4*)(z + (tok0 + row) * DD);
    float d = 0.0f;
#pragma unroll
    for (int i = 0; i < DD / 4; ++i) {
        float4 a = rw[i], b = zr[i];
        d = __fmaf_rn(a.x, b.x, d); d = __fmaf_rn(a.y, b.y, d);
        d = __fmaf_rn(a.z, b.z, d); d = __fmaf_rn(a.w, b.w, d);
    }
    float e = __fsub_rn(__fadd_rn(s_S[row], s_c2[k]), __fmul_rn(2.0f, d));
    u64 pack = ((u64)__float_as_uint(e) << 32) | (unsigned)k;
    atomicMin(&s_cand[row], pack);
}

__global__ void __launch_bounds__(TPB, 2) vq_coal(const float* __restrict__ z,
                                                  const float* __restrict__ cb,
                                                  float* __restrict__ out,
                                                  int loss_idx) {
    extern __shared__ char sm[];
    __nv_bfloat16* s_z = (__nv_bfloat16*)(sm + OFF_Z);
    float*  s_c2   = (float*)(sm + OFF_C2);
    float2* s_c2p  = (float2*)(sm + OFF_C2);
    float*  s_S    = (float*)(sm + OFF_S);
    u64*    s_cand = (u64*)(sm + OFF_CAND);
    float*  s_minw = (float*)(sm + OFF_MINW);
    unsigned* s_q  = (unsigned*)(sm + OFF_Q);
    int*    s_qc   = (int*)(sm + OFF_QC);
    double* s_red  = (double*)(sm + OFF_RED);

    const int tid = threadIdx.x, wid = tid >> 5, lane = tid & 31;
    const int g = lane >> 2, tg = lane & 3;
    const int tgrp = wid >> 1;        // token group (32 tokens)
    const int cgrp = wid & 1;         // code group (256 codes)
    const float FINF = __int_as_float(0x7f800000);

    // ---- one-time: pair-packed bf16 codebook + exact fp32 norms ----
    {
        const float4* cf = (const float4*)cb;
        for (int idx = tid; idx < KC * DD / 4; idx += TPB) {
            int n = idx >> 4, c4 = idx & 15;
            float4 v = cf[idx];
            int k0 = c4 * 4;
            int ks = k0 >> 4;
            int r0 = k0 & 15, r1 = r0 + 2;
            char* base = sm + OFF_CBP + n * 144 + ks * 32;
            *(__nv_bfloat162*)(base + ((r0 >> 1) & 3) * 8 + (r0 >> 3) * 4) =
                __floats2bfloat162_rn(v.x, v.y);
            *(__nv_bfloat162*)(base + ((r1 >> 1) & 3) * 8 + (r1 >> 3) * 4) =
                __floats2bfloat162_rn(v.z, v.w);
        }
        for (int k = tid; k < KC; k += TPB) {
            const float4* r = (const float4*)(cb + (size_t)k * DD);
            float s = 0.0f;
#pragma unroll
            for (int i = 0; i < DD / 4; ++i) {
                float4 v = r[i];
                s = __fmaf_rn(v.x, v.x, s); s = __fmaf_rn(v.y, v.y, s);
                s = __fmaf_rn(v.z, v.z, s); s = __fmaf_rn(v.w, v.w, s);
            }
            s_c2[k] = s;
        }
    }

    double my_loss = 0.0;

    for (int tile = blockIdx.x; tile < NTILE; tile += GRIDP) {
        const size_t tok0 = (size_t)tile * TK;

        // ---- per-tile: COALESCED bf16 z row tile (R8-proven fill) ----
        {
            const float4* zf = (const float4*)(z + tok0 * DD);
            for (int idx = tid; idx < TK * DD / 4; idx += TPB) {
                int row = idx >> 4, c4 = idx & 15;
                float4 v = zf[idx];
                __nv_bfloat16* p = s_z + row * RS + c4 * 4;
                *(__nv_bfloat162*)(p)     = __floats2bfloat162_rn(v.x, v.y);
                *(__nv_bfloat162*)(p + 2) = __floats2bfloat162_rn(v.z, v.w);
            }
        }
        // exact S, sequential per token (order must match ref; spread 8 warps)
        if ((tid & 1) == 0) {
            const int t = tid >> 1;
            const float4* r = (const float4*)(z + (tok0 + t) * DD);
            float s = 0.0f;
#pragma unroll
            for (int i = 0; i < DD / 4; ++i) {
                float4 v = r[i];
                s = __fmaf_rn(v.x, v.x, s); s = __fmaf_rn(v.y, v.y, s);
                s = __fmaf_rn(v.z, v.z, s); s = __fmaf_rn(v.w, v.w, s);
            }
            s_S[t] = s;
            s_cand[t] = 0xFFFFFFFFFFFFFFFFull;
        }
        if (tid == 0) *s_qc = 0;
        __syncthreads();

        // ---- A fragments from bf16 row tile (cold scattered LDS.32) ----
        unsigned aF[2][4][4];
#pragma unroll
        for (int mt = 0; mt < 2; ++mt) {
            const int rlo = tgrp * 32 + mt * 16 + g;
#pragma unroll
            for (int ks = 0; ks < 4; ++ks) {
                const __nv_bfloat16* pl = s_z + rlo * RS + tg * 2 + 16 * ks;
                aF[mt][ks][0] = *(const unsigned*)pl;
                aF[mt][ks][1] = *(const unsigned*)(pl + 8 * RS);
                aF[mt][ks][2] = *(const unsigned*)(pl + 8);
                aF[mt][ks][3] = *(const unsigned*)(pl + 8 * RS + 8);
            }
        }

        const char* pw = sm + OFF_CBP + (cgrp * 256) * 144 + g * 144 + tg * 8;
        const int row0 = tgrp * 32 + g;

        // ========== Pass 1: per-token approx mins (R13-proven) =============
        float mn00 = FINF, mn01 = FINF, mn10 = FINF, mn11 = FINF;
        {
            uint2 bC0 = *(const uint2*)(pw),      bC1 = *(const uint2*)(pw + 32);
            uint2 bC2 = *(const uint2*)(pw + 64), bC3 = *(const uint2*)(pw + 96);
#pragma unroll 1
            for (int j = 0; j < 32; ++j) {
                const char* pn = pw + j * 1152 + 1152;
                uint2 n0, n1, n2, n3;
                if (j < 31) {
                    n0 = *(const uint2*)(pn);      n1 = *(const uint2*)(pn + 32);
                    n2 = *(const uint2*)(pn + 64); n3 = *(const uint2*)(pn + 96);
                }
                float a0[4] = {0, 0, 0, 0}, a1[4] = {0, 0, 0, 0};
                mma16816(a0, aF[0][0], bC0.x, bC0.y); mma16816(a1, aF[1][0], bC0.x, bC0.y);
                mma16816(a0, aF[0][1], bC1.x, bC1.y); mma16816(a1, aF[1][1], bC1.x, bC1.y);
                mma16816(a0, aF[0][2], bC2.x, bC2.y); mma16816(a1, aF[1][2], bC2.x, bC2.y);
                mma16816(a0, aF[0][3], bC3.x, bC3.y); mma16816(a1, aF[1][3], bC3.x, bC3.y);
                float2 cc = s_c2p[cgrp * 128 + 4 * j + tg];
                mn00 = fminf(mn00, fminf(__fmaf_rn(-2.0f, a0[0], cc.x),
                                         __fmaf_rn(-2.0f, a0[1], cc.y)));
                mn01 = fminf(mn01, fminf(__fmaf_rn(-2.0f, a0[2], cc.x),
                                         __fmaf_rn(-2.0f, a0[3], cc.y)));
                mn10 = fminf(mn10, fminf(__fmaf_rn(-2.0f, a1[0], cc.x),
                                         __fmaf_rn(-2.0f, a1[1], cc.y)));
                mn11 = fminf(mn11, fminf(__fmaf_rn(-2.0f, a1[2], cc.x),
                                         __fmaf_rn(-2.0f, a1[3], cc.y)));
                bC0 = n0; bC1 = n1; bC2 = n2; bC3 = n3;
            }
        }
        mn00 = fminf(mn00, __shfl_xor_sync(0xFFFFFFFFu, mn00, 1));
        mn00 = fminf(mn00, __shfl_xor_sync(0xFFFFFFFFu, mn00, 2));
        mn01 = fminf(mn01, __shfl_xor_sync(0xFFFFFFFFu, mn01, 1));
        mn01 = fminf(mn01, __shfl_xor_sync(0xFFFFFFFFu, mn01, 2));
        mn10 = fminf(mn10, __shfl_xor_sync(0xFFFFFFFFu, mn10, 1));
        mn10 = fminf(mn10, __shfl_xor_sync(0xFFFFFFFFu, mn10, 2));
        mn11 = fminf(mn11, __shfl_xor_sync(0xFFFFFFFFu, mn11, 1));
        mn11 = fminf(mn11, __shfl_xor_sync(0xFFFFFFFFu, mn11, 2));
        if (tg == 0) {
            s_minw[(row0)      * 2 + cgrp] = mn00;
            s_minw[(row0 + 8)  * 2 + cgrp] = mn01;
            s_minw[(row0 + 16) * 2 + cgrp] = mn10;
            s_minw[(row0 + 24) * 2 + cgrp] = mn11;
        }
        __syncthreads();

        const float thr00 = fminf(s_minw[(row0)      * 2], s_minw[(row0)      * 2 + 1]) + WIN;
        const float thr01 = fminf(s_minw[(row0 + 8)  * 2], s_minw[(row0 + 8)  * 2 + 1]) + WIN;
        const float thr10 = fminf(s_minw[(row0 + 16) * 2], s_minw[(row0 + 16) * 2 + 1]) + WIN;
        const float thr11 = fminf(s_minw[(row0 + 24) * 2], s_minw[(row0 + 24) * 2 + 1]) + WIN;

        // ========== Pass 2: window hits -> queue (R13-proven) ==============
        {
            uint2 bC0 = *(const uint2*)(pw),      bC1 = *(const uint2*)(pw + 32);
            uint2 bC2 = *(const uint2*)(pw + 64), bC3 = *(const uint2*)(pw + 96);
#pragma unroll 1
            for (int j = 0; j < 32; ++j) {
                const char* pn = pw + j * 1152 + 1152;
                uint2 n0, n1, n2, n3;
                if (j < 31) {
                    n0 = *(const uint2*)(pn);      n1 = *(const uint2*)(pn + 32);
                    n2 = *(const uint2*)(pn + 64); n3 = *(const uint2*)(pn + 96);
                }
                float a0[4] = {0, 0, 0, 0}, a1[4] = {0, 0, 0, 0};
                mma16816(a0, aF[0][0], bC0.x, bC0.y); mma16816(a1, aF[1][0], bC0.x, bC0.y);
                mma16816(a0, aF[0][1], bC1.x, bC1.y); mma16816(a1, aF[1][1], bC1.x, bC1.y);
                mma16816(a0, aF[0][2], bC2.x, bC2.y); mma16816(a1, aF[1][2], bC2.x, bC2.y);
                mma16816(a0, aF[0][3], bC3.x, bC3.y); mma16816(a1, aF[1][3], bC3.x, bC3.y);
                float2 cc = s_c2p[cgrp * 128 + 4 * j + tg];
                const int c0 = cgrp * 256 + 8 * j + tg * 2;
                float s0 = __fmaf_rn(-2.0f, a0[0], cc.x);
                float s1 = __fmaf_rn(-2.0f, a0[1], cc.y);
                float s2 = __fmaf_rn(-2.0f, a0[2], cc.x);
                float s3 = __fmaf_rn(-2.0f, a0[3], cc.y);
                float s4 = __fmaf_rn(-2.0f, a1[0], cc.x);
                float s5 = __fmaf_rn(-2.0f, a1[1], cc.y);
                float s6 = __fmaf_rn(-2.0f, a1[2], cc.x);
                float s7 = __fmaf_rn(-2.0f, a1[3], cc.y);
                if (s0 < thr00) { int sl = atomicAdd(s_qc, 1); if (sl < QCAP) s_q[sl] = (unsigned)((row0 << 9) | c0); }
                if (s1 < thr00) { int sl = atomicAdd(s_qc, 1); if (sl < QCAP) s_q[sl] = (unsigned)((row0 << 9) | (c0 + 1)); }
                if (s2 < thr01) { int sl = atomicAdd(s_qc, 1); if (sl < QCAP) s_q[sl] = (unsigned)(((row0 + 8) << 9) | c0); }
                if (s3 < thr01) { int sl = atomicAdd(s_qc, 1); if (sl < QCAP) s_q[sl] = (unsigned)(((row0 + 8) << 9) | (c0 + 1)); }
                if (s4 < thr10) { int sl = atomicAdd(s_qc, 1); if (sl < QCAP) s_q[sl] = (unsigned)(((row0 + 16) << 9) | c0); }
                if (s5 < thr10) { int sl = atomicAdd(s_qc, 1); if (sl < QCAP) s_q[sl] = (unsigned)(((row0 + 16) << 9) | (c0 + 1)); }
                if (s6 < thr11) { int sl = atomicAdd(s_qc, 1); if (sl < QCAP) s_q[sl] = (unsigned)(((row0 + 24) << 9) | c0); }
                if (s7 < thr11) { int sl = atomicAdd(s_qc, 1); if (sl < QCAP) s_q[sl] = (unsigned)(((row0 + 24) << 9) | (c0 + 1)); }
                bC0 = n0; bC1 = n1; bC2 = n2; bC3 = n3;
            }
        }
        __syncthreads();

        // ---- Drain queue: cooperative exact rescore ----
        {
            int nq = *s_qc;
            if (nq > QCAP) {
                if (tid < TK) {   // overflow (prob ~0): full exact scan
                    float S = s_S[tid];
                    u64 best = 0xFFFFFFFFFFFFFFFFull;
                    for (int k = 0; k < KC; ++k) {
                        const float4* rw = (const float4*)(cb + (size_t)k * DD);
                        const float4* zr = (const float4*)(z + (tok0 + tid) * DD);
                        float d = 0.0f;
#pragma unroll
                        for (int i = 0; i < DD / 4; ++i) {
                            float4 a = rw[i], b = zr[i];
                            d = __fmaf_rn(a.x, b.x, d); d = __fmaf_rn(a.y, b.y, d);
                            d = __fmaf_rn(a.z, b.z, d); d = __fmaf_rn(a.w, b.w, d);
                        }
                        float e = __fsub_rn(__fadd_rn(S, s_c2[k]), __fmul_rn(2.0f, d));
                        u64 p = ((u64)__float_as_uint(e) << 32) | (unsigned)k;
                        if (p < best) best = p;
                    }
                    atomicMin(&s_cand[tid], best);
                }
            } else {
                for (int i = tid; i < nq; i += TPB) {
                    unsigned e = s_q[i];
                    rescore(z, cb, s_c2, s_S, s_cand, tok0, (int)(e >> 9), (int)(e & 511u));
                }
            }
        }
        __syncthreads();

        // ---- Epilogue: flat-coalesced STE output + loss (all 256 threads) --
        {
            float lacc = 0.0f;
#pragma unroll
            for (int i = 0; i < 8; ++i) {
                const int f = i * TPB + tid;         // float4 unit 0..2047
                const int token = f >> 4, q4 = f & 15;
                const int bk = (int)(s_cand[token] & 0xFFFFFFFFull);
                float4 cv = ((const float4*)(cb + (size_t)bk * DD))[q4];
                float4 zv = ((const float4*)(z + (tok0 + token) * DD))[q4];
                float4 o; float dx;
                dx = __fsub_rn(cv.x, zv.x); o.x = __fadd_rn(zv.x, dx); lacc = __fmaf_rn(dx, dx, lacc);
                dx = __fsub_rn(cv.y, zv.y); o.y = __fadd_rn(zv.y, dx); lacc = __fmaf_rn(dx, dx, lacc);
                dx = __fsub_rn(cv.z, zv.z); o.z = __fadd_rn(zv.z, dx); lacc = __fmaf_rn(dx, dx, lacc);
                dx = __fsub_rn(cv.w, zv.w); o.w = __fadd_rn(zv.w, dx); lacc = __fmaf_rn(dx, dx, lacc);
                ((float4*)(out + tok0 * DD))[f] = o;
            }
            my_loss += (double)lacc;
        }
        __syncthreads();
    }

    // ---- final loss reduction ----
    double dacc = my_loss;
#pragma unroll
    for (int o = 16; o > 0; o >>= 1)
        dacc += __shfl_down_sync(0xFFFFFFFFu, dacc, o);
    if (lane == 0) s_red[wid] = dacc;
    __syncthreads();
    if (tid == 0) {
        double t = 0.0;
#pragma unroll
        for (int w = 0; w < TPB / 32; ++w) t += s_red[w];
        atomicAdd(&g_loss_acc, t);
        __threadfence();
        unsigned int prev = atomicAdd(&g_done_ctr, 1u);
        if (prev == GRIDP - 1) {
            double m = atomicAdd(&g_loss_acc, 0.0) / (double)((long long)NT * DD);
            float m32 = (float)m;
            out[loss_idx] = __fadd_rn(m32, __fmul_rn(0.25f, m32));
            g_loss_acc = 0.0;
            __threadfence();
            g_done_ctr = 0u;
        }
    }
}

extern "C" void kernel_launch(void* const* d_in, const int* in_sizes, int n_in,
                              void* d_out, int out_size) {
    const float* z;
    const float* cb;
    if (in_sizes[0] == NT * DD) {
        z = (const float*)d_in[0];
        cb = (const float*)d_in[1];
    } else {
        z = (const float*)d_in[1];
        cb = (const float*)d_in[0];
    }
    float* out = (float*)d_out;

    cudaFuncSetAttribute(vq_coal, cudaFuncAttributeMaxDynamicSharedMemorySize,
                         SMEM_TOTAL);
    vq_coal<<<GRIDP, TPB, SMEM_TOTAL>>>(z, cb, out, out_size - 1);
}

// round 17
// speedup vs baseline: 1.4257x; 1.0452x over previous
#include <cuda_runtime.h>
#include <cuda_bf16.h>
#include <cstdint>

#define NT     262144
#define KC     512
#define DD     64
#define TPB    256
#define TK     128
#define NTILE  (NT / TK)
#define GRIDP  296
#define WIN    3.0e-3f
#define QCAP   1024
#define RS     72                      // z-tile row stride in bf16 (144B)

// smem layout
#define OFF_Z    0                      // bf16 z row tile 128*144 = 18432
#define OFF_CBP  18432                  // packed codebook 512*144 = 73728
#define OFF_C2   (OFF_CBP + 73728)      // 92160: fp32 norms [512]
#define OFF_S    (OFF_C2 + 2048)        // 94208: per-token S [128]
#define OFF_CAND (OFF_S + 512)          // 94720: packed (e,k) [128] u64
#define OFF_MINW (OFF_CAND + 1024)      // 95744: per-token per-cgrp mins [128][2]
#define OFF_Q    (OFF_MINW + 1024)      // 96768: hit queue u32 [1024]
#define OFF_QC   (OFF_Q + 4096)         // 100864
#define OFF_RED  (OFF_QC + 16)          // 100880
#define SMEM_TOTAL (OFF_RED + 64)       // 100944 -> 2 CTAs/SM

typedef unsigned long long u64;

__device__ double g_loss_acc;
__device__ unsigned int g_done_ctr;

__device__ __forceinline__ void mma16816(float* d, const unsigned* a,
                                         unsigned b0, unsigned b1) {
    asm volatile(
        "mma.sync.aligned.m16n8k16.row.col.f32.bf16.bf16.f32 "
        "{%0,%1,%2,%3}, {%4,%5,%6,%7}, {%8,%9}, {%0,%1,%2,%3};"
        : "+f"(d[0]), "+f"(d[1]), "+f"(d[2]), "+f"(d[3])
        : "r"(a[0]), "r"(a[1]), "r"(a[2]), "r"(a[3]), "r"(b0), "r"(b1));
}

// Exact rescore (R2-proven rounding: fl(fl(S+c2)-fl(2*dot)), sequential
// ascending-d fp32 FMA) + packed atomicMin (equal e -> lower k = jnp ties).
__device__ __forceinline__ void rescore(const float* __restrict__ z,
                                        const float* __restrict__ cb,
                                        const float* s_c2, const float* s_S,
                                        u64* s_cand, size_t tok0, int row, int k) {
    const float4* rw = (const float4*)(cb + (size_t)k * DD);
    const float4* zr = (const float4*)(z + (tok0 + row) * DD);
    float d = 0.0f;
#pragma unroll
    for (int i = 0; i < DD / 4; ++i) {
        float4 a = rw[i], b = zr[i];
        d = __fmaf_rn(a.x, b.x, d); d = __fmaf_rn(a.y, b.y, d);
        d = __fmaf_rn(a.z, b.z, d); d = __fmaf_rn(a.w, b.w, d);
    }
    float e = __fsub_rn(__fadd_rn(s_S[row], s_c2[k]), __fmul_rn(2.0f, d));
    u64 pack = ((u64)__float_as_uint(e) << 32) | (unsigned)k;
    atomicMin(&s_cand[row], pack);
}

__global__ void __launch_bounds__(TPB, 2) vq_w128(const float* __restrict__ z,
                                                  const float* __restrict__ cb,
                                                  float* __restrict__ out,
                                                  int loss_idx) {
    extern __shared__ char sm[];
    __nv_bfloat16* s_z = (__nv_bfloat16*)(sm + OFF_Z);
    float*  s_c2   = (float*)(sm + OFF_C2);
    float2* s_c2p  = (float2*)(sm + OFF_C2);
    float*  s_S    = (float*)(sm + OFF_S);
    u64*    s_cand = (u64*)(sm + OFF_CAND);
    float*  s_minw = (float*)(sm + OFF_MINW);
    unsigned* s_q  = (unsigned*)(sm + OFF_Q);
    int*    s_qc   = (int*)(sm + OFF_QC);
    double* s_red  = (double*)(sm + OFF_RED);

    const int tid = threadIdx.x, wid = tid >> 5, lane = tid & 31;
    const int g = lane >> 2, tg = lane & 3;
    const int tgrp = wid >> 1;        // token group (32 tokens)
    const int cgrp = wid & 1;         // code group (256 codes)
    const float FINF = __int_as_float(0x7f800000);

    // ---- one-time: LDS.128-packed bf16 codebook + exact fp32 norms ----
    // Lane (g,tg) unit for code n: 16B [ks0-pair | ks1-pair] at n*144+tg*16,
    //                              16B [ks2-pair | ks3-pair] at +64.
    // 8B pair content identical to R16: cols {2tg,2tg+1} lo, {2tg+8,2tg+9} hi.
    {
        const float4* cf = (const float4*)cb;
        for (int idx = tid; idx < KC * DD / 4; idx += TPB) {
            int n = idx >> 4, c4 = idx & 15;
            float4 v = cf[idx];
            int k0 = c4 * 4;
            int ks = k0 >> 4;
            int r0 = k0 & 15, r1 = r0 + 2;
            char* base = sm + OFF_CBP + n * 144 + (ks >> 1) * 64 + (ks & 1) * 8;
            *(__nv_bfloat162*)(base + ((r0 >> 1) & 3) * 16 + (r0 >> 3) * 4) =
                __floats2bfloat162_rn(v.x, v.y);
            *(__nv_bfloat162*)(base + ((r1 >> 1) & 3) * 16 + (r1 >> 3) * 4) =
                __floats2bfloat162_rn(v.z, v.w);
        }
        for (int k = tid; k < KC; k += TPB) {
            const float4* r = (const float4*)(cb + (size_t)k * DD);
            float s = 0.0f;
#pragma unroll
            for (int i = 0; i < DD / 4; ++i) {
                float4 v = r[i];
                s = __fmaf_rn(v.x, v.x, s); s = __fmaf_rn(v.y, v.y, s);
                s = __fmaf_rn(v.z, v.z, s); s = __fmaf_rn(v.w, v.w, s);
            }
            s_c2[k] = s;
        }
    }

    double my_loss = 0.0;

    for (int tile = blockIdx.x; tile < NTILE; tile += GRIDP) {
        const size_t tok0 = (size_t)tile * TK;

        // ---- per-tile: coalesced bf16 z row tile ----
        {
            const float4* zf = (const float4*)(z + tok0 * DD);
            for (int idx = tid; idx < TK * DD / 4; idx += TPB) {
                int row = idx >> 4, c4 = idx & 15;
                float4 v = zf[idx];
                __nv_bfloat16* p = s_z + row * RS + c4 * 4;
                *(__nv_bfloat162*)(p)     = __floats2bfloat162_rn(v.x, v.y);
                *(__nv_bfloat162*)(p + 2) = __floats2bfloat162_rn(v.z, v.w);
            }
        }
        // exact S, sequential per token (order-stable; spread over 8 warps)
        if ((tid & 1) == 0) {
            const int t = tid >> 1;
            const float4* r = (const float4*)(z + (tok0 + t) * DD);
            float s = 0.0f;
#pragma unroll
            for (int i = 0; i < DD / 4; ++i) {
                float4 v = r[i];
                s = __fmaf_rn(v.x, v.x, s); s = __fmaf_rn(v.y, v.y, s);
                s = __fmaf_rn(v.z, v.z, s); s = __fmaf_rn(v.w, v.w, s);
            }
            s_S[t] = s;
            s_cand[t] = 0xFFFFFFFFFFFFFFFFull;
        }
        if (tid == 0) *s_qc = 0;
        __syncthreads();

        // ---- A fragments from bf16 row tile (cold) ----
        unsigned aF[2][4][4];
#pragma unroll
        for (int mt = 0; mt < 2; ++mt) {
            const int rlo = tgrp * 32 + mt * 16 + g;
#pragma unroll
            for (int ks = 0; ks < 4; ++ks) {
                const __nv_bfloat16* pl = s_z + rlo * RS + tg * 2 + 16 * ks;
                aF[mt][ks][0] = *(const unsigned*)pl;
                aF[mt][ks][1] = *(const unsigned*)(pl + 8 * RS);
                aF[mt][ks][2] = *(const unsigned*)(pl + 8);
                aF[mt][ks][3] = *(const unsigned*)(pl + 8 * RS + 8);
            }
        }

        const char* pw = sm + OFF_CBP + (cgrp * 256) * 144 + g * 144 + tg * 16;
        const int row0 = tgrp * 32 + g;

        // ========== Pass 1: per-token approx mins (2x LDS.128/j) ===========
        float mn00 = FINF, mn01 = FINF, mn10 = FINF, mn11 = FINF;
        {
            uint4 bE = *(const uint4*)(pw);        // ks0,ks1
            uint4 bO = *(const uint4*)(pw + 64);   // ks2,ks3
#pragma unroll 1
            for (int j = 0; j < 32; ++j) {
                const char* pn = pw + j * 1152 + 1152;
                uint4 nE, nO;
                if (j < 31) {
                    nE = *(const uint4*)(pn);
                    nO = *(const uint4*)(pn + 64);
                }
                float a0[4] = {0, 0, 0, 0}, a1[4] = {0, 0, 0, 0};
                mma16816(a0, aF[0][0], bE.x, bE.y); mma16816(a1, aF[1][0], bE.x, bE.y);
                mma16816(a0, aF[0][1], bE.z, bE.w); mma16816(a1, aF[1][1], bE.z, bE.w);
                mma16816(a0, aF[0][2], bO.x, bO.y); mma16816(a1, aF[1][2], bO.x, bO.y);
                mma16816(a0, aF[0][3], bO.z, bO.w); mma16816(a1, aF[1][3], bO.z, bO.w);
                float2 cc = s_c2p[cgrp * 128 + 4 * j + tg];
                mn00 = fminf(mn00, fminf(__fmaf_rn(-2.0f, a0[0], cc.x),
                                         __fmaf_rn(-2.0f, a0[1], cc.y)));
                mn01 = fminf(mn01, fminf(__fmaf_rn(-2.0f, a0[2], cc.x),
                                         __fmaf_rn(-2.0f, a0[3], cc.y)));
                mn10 = fminf(mn10, fminf(__fmaf_rn(-2.0f, a1[0], cc.x),
                                         __fmaf_rn(-2.0f, a1[1], cc.y)));
                mn11 = fminf(mn11, fminf(__fmaf_rn(-2.0f, a1[2], cc.x),
                                         __fmaf_rn(-2.0f, a1[3], cc.y)));
                bE = nE; bO = nO;
            }
        }
        mn00 = fminf(mn00, __shfl_xor_sync(0xFFFFFFFFu, mn00, 1));
        mn00 = fminf(mn00, __shfl_xor_sync(0xFFFFFFFFu, mn00, 2));
        mn01 = fminf(mn01, __shfl_xor_sync(0xFFFFFFFFu, mn01, 1));
        mn01 = fminf(mn01, __shfl_xor_sync(0xFFFFFFFFu, mn01, 2));
        mn10 = fminf(mn10, __shfl_xor_sync(0xFFFFFFFFu, mn10, 1));
        mn10 = fminf(mn10, __shfl_xor_sync(0xFFFFFFFFu, mn10, 2));
        mn11 = fminf(mn11, __shfl_xor_sync(0xFFFFFFFFu, mn11, 1));
        mn11 = fminf(mn11, __shfl_xor_sync(0xFFFFFFFFu, mn11, 2));
        if (tg == 0) {
            s_minw[(row0)      * 2 + cgrp] = mn00;
            s_minw[(row0 + 8)  * 2 + cgrp] = mn01;
            s_minw[(row0 + 16) * 2 + cgrp] = mn10;
            s_minw[(row0 + 24) * 2 + cgrp] = mn11;
        }
        __syncthreads();

        const float thr00 = fminf(s_minw[(row0)      * 2], s_minw[(row0)      * 2 + 1]) + WIN;
        const float thr01 = fminf(s_minw[(row0 + 8)  * 2], s_minw[(row0 + 8)  * 2 + 1]) + WIN;
        const float thr10 = fminf(s_minw[(row0 + 16) * 2], s_minw[(row0 + 16) * 2 + 1]) + WIN;
        const float thr11 = fminf(s_minw[(row0 + 24) * 2], s_minw[(row0 + 24) * 2 + 1]) + WIN;

        // ========== Pass 2: window hits -> queue (2x LDS.128/j) ============
        {
            uint4 bE = *(const uint4*)(pw);
            uint4 bO = *(const uint4*)(pw + 64);
#pragma unroll 1
            for (int j = 0; j < 32; ++j) {
                const char* pn = pw + j * 1152 + 1152;
                uint4 nE, nO;
                if (j < 31) {
                    nE = *(const uint4*)(pn);
                    nO = *(const uint4*)(pn + 64);
                }
                float a0[4] = {0, 0, 0, 0}, a1[4] = {0, 0, 0, 0};
                mma16816(a0, aF[0][0], bE.x, bE.y); mma16816(a1, aF[1][0], bE.x, bE.y);
                mma16816(a0, aF[0][1], bE.z, bE.w); mma16816(a1, aF[1][1], bE.z, bE.w);
                mma16816(a0, aF[0][2], bO.x, bO.y); mma16816(a1, aF[1][2], bO.x, bO.y);
                mma16816(a0, aF[0][3], bO.z, bO.w); mma16816(a1, aF[1][3], bO.z, bO.w);
                float2 cc = s_c2p[cgrp * 128 + 4 * j + tg];
                const int c0 = cgrp * 256 + 8 * j + tg * 2;
                float s0 = __fmaf_rn(-2.0f, a0[0], cc.x);
                float s1 = __fmaf_rn(-2.0f, a0[1], cc.y);
                float s2 = __fmaf_rn(-2.0f, a0[2], cc.x);
                float s3 = __fmaf_rn(-2.0f, a0[3], cc.y);
                float s4 = __fmaf_rn(-2.0f, a1[0], cc.x);
                float s5 = __fmaf_rn(-2.0f, a1[1], cc.y);
                float s6 = __fmaf_rn(-2.0f, a1[2], cc.x);
                float s7 = __fmaf_rn(-2.0f, a1[3], cc.y);
                if (s0 < thr00) { int sl = atomicAdd(s_qc, 1); if (sl < QCAP) s_q[sl] = (unsigned)((row0 << 9) | c0); }
                if (s1 < thr00) { int sl = atomicAdd(s_qc, 1); if (sl < QCAP) s_q[sl] = (unsigned)((row0 << 9) | (c0 + 1)); }
                if (s2 < thr01) { int sl = atomicAdd(s_qc, 1); if (sl < QCAP) s_q[sl] = (unsigned)(((row0 + 8) << 9) | c0); }
                if (s3 < thr01) { int sl = atomicAdd(s_qc, 1); if (sl < QCAP) s_q[sl] = (unsigned)(((row0 + 8) << 9) | (c0 + 1)); }
                if (s4 < thr10) { int sl = atomicAdd(s_qc, 1); if (sl < QCAP) s_q[sl] = (unsigned)(((row0 + 16) << 9) | c0); }
                if (s5 < thr10) { int sl = atomicAdd(s_qc, 1); if (sl < QCAP) s_q[sl] = (unsigned)(((row0 + 16) << 9) | (c0 + 1)); }
                if (s6 < thr11) { int sl = atomicAdd(s_qc, 1); if (sl < QCAP) s_q[sl] = (unsigned)(((row0 + 24) << 9) | c0); }
                if (s7 < thr11) { int sl = atomicAdd(s_qc, 1); if (sl < QCAP) s_q[sl] = (unsigned)(((row0 + 24) << 9) | (c0 + 1)); }
                bE = nE; bO = nO;
            }
        }
        __syncthreads();

        // ---- Drain queue: cooperative exact rescore ----
        {
            int nq = *s_qc;
            if (nq > QCAP) {
                if (tid < TK) {   // overflow (prob ~0): full exact scan
                    float S = s_S[tid];
                    u64 best = 0xFFFFFFFFFFFFFFFFull;
                    for (int k = 0; k < KC; ++k) {
                        const float4* rw = (const float4*)(cb + (size_t)k * DD);
                        const float4* zr = (const float4*)(z + (tok0 + tid) * DD);
                        float d = 0.0f;
#pragma unroll
                        for (int i = 0; i < DD / 4; ++i) {
                            float4 a = rw[i], b = zr[i];
                            d = __fmaf_rn(a.x, b.x, d); d = __fmaf_rn(a.y, b.y, d);
                            d = __fmaf_rn(a.z, b.z, d); d = __fmaf_rn(a.w, b.w, d);
                        }
                        float e = __fsub_rn(__fadd_rn(S, s_c2[k]), __fmul_rn(2.0f, d));
                        u64 p = ((u64)__float_as_uint(e) << 32) | (unsigned)k;
                        if (p < best) best = p;
                    }
                    atomicMin(&s_cand[tid], best);
                }
            } else {
                for (int i = tid; i < nq; i += TPB) {
                    unsigned e = s_q[i];
                    rescore(z, cb, s_c2, s_S, s_cand, tok0, (int)(e >> 9), (int)(e & 511u));
                }
            }
        }
        __syncthreads();

        // ---- Epilogue: flat-coalesced STE output + loss (all 256 threads) --
        {
            float lacc = 0.0f;
#pragma unroll
            for (int i = 0; i < 8; ++i) {
                const int f = i * TPB + tid;         // float4 unit 0..2047
                const int token = f >> 4, q4 = f & 15;
                const int bk = (int)(s_cand[token] & 0xFFFFFFFFull);
                float4 cv = ((const float4*)(cb + (size_t)bk * DD))[q4];
                float4 zv = ((const float4*)(z + (tok0 + token) * DD))[q4];
                float4 o; float dx;
                dx = __fsub_rn(cv.x, zv.x); o.x = __fadd_rn(zv.x, dx); lacc = __fmaf_rn(dx, dx, lacc);
                dx = __fsub_rn(cv.y, zv.y); o.y = __fadd_rn(zv.y, dx); lacc = __fmaf_rn(dx, dx, lacc);
                dx = __fsub_rn(cv.z, zv.z); o.z = __fadd_rn(zv.z, dx); lacc = __fmaf_rn(dx, dx, lacc);
                dx = __fsub_rn(cv.w, zv.w); o.w = __fadd_rn(zv.w, dx); lacc = __fmaf_rn(dx, dx, lacc);
                ((float4*)(out + tok0 * DD))[f] = o;
            }
            my_loss += (double)lacc;
        }
        __syncthreads();
    }

    // ---- final loss reduction ----
    double dacc = my_loss;
#pragma unroll
    for (int o = 16; o > 0; o >>= 1)
        dacc += __shfl_down_sync(0xFFFFFFFFu, dacc, o);
    if (lane == 0) s_red[wid] = dacc;
    __syncthreads();
    if (tid == 0) {
        double t = 0.0;
#pragma unroll
        for (int w = 0; w < TPB / 32; ++w) t += s_red[w];
        atomicAdd(&g_loss_acc, t);
        __threadfence();
        unsigned int prev = atomicAdd(&g_done_ctr, 1u);
        if (prev == GRIDP - 1) {
            double m = atomicAdd(&g_loss_acc, 0.0) / (double)((long long)NT * DD);
            float m32 = (float)m;
            out[loss_idx] = __fadd_rn(m32, __fmul_rn(0.25f, m32));
            g_loss_acc = 0.0;
            __threadfence();
            g_done_ctr = 0u;
        }
    }
}

extern "C" void kernel_launch(void* const* d_in, const int* in_sizes, int n_in,
                              void* d_out, int out_size) {
    const float* z;
    const float* cb;
    if (in_sizes[0] == NT * DD) {
        z = (const float*)d_in[0];
        cb = (const float*)d_in[1];
    } else {
        z = (const float*)d_in[1];
        cb = (const float*)d_in[0];
    }
    float* out = (float*)d_out;

    cudaFuncSetAttribute(vq_w128, cudaFuncAttributeMaxDynamicSharedMemorySize,
                         SMEM_TOTAL);
    vq_w128<<<GRIDP, TPB, SMEM_TOTAL>>>(z, cb, out, out_size - 1);
}